// round 1
// baseline (speedup 1.0000x reference)
#include <cuda_runtime.h>

#define N_NODES 100000
#define N_EDGES 1600000
#define HID 128

// Scratch (no cudaMalloc allowed). Zero-fill .bss-style, 16B aligned for float4.
__device__ __align__(16) float g_A[(size_t)N_NODES * HID];   // GEMM output / message source
__device__ __align__(16) float g_B[(size_t)N_NODES * HID];   // aggregation accumulator
__device__ __align__(16) float g_deg[N_NODES];
__device__ __align__(16) float g_dinv[N_NODES];
__device__ __align__(16) float g_norm[N_EDGES];

// ---------------- normalization precompute ----------------
__global__ void k_deg_init() {
    int i = blockIdx.x * blockDim.x + threadIdx.x;
    if (i < N_NODES) g_deg[i] = 1.0f;   // self-loop
}

__global__ void k_deg_accum(const int* __restrict__ dst) {
    int e = blockIdx.x * blockDim.x + threadIdx.x;
    if (e < N_EDGES) atomicAdd(&g_deg[dst[e]], 1.0f);
}

__global__ void k_dinv() {
    int i = blockIdx.x * blockDim.x + threadIdx.x;
    if (i < N_NODES) g_dinv[i] = rsqrtf(g_deg[i]);   // deg >= 1 always (self-loop)
}

__global__ void k_norm(const int* __restrict__ src, const int* __restrict__ dst) {
    int e = blockIdx.x * blockDim.x + threadIdx.x;
    if (e < N_EDGES) g_norm[e] = g_dinv[src[e]] * g_dinv[dst[e]];
}

// ---------------- layer-1 GEMM: A = x @ W1   (K = 5) ----------------
__global__ __launch_bounds__(128) void k_gemm_in(const float* __restrict__ x,
                                                 const float* __restrict__ W1) {
    __shared__ float Ws[5 * HID];
    int tid = threadIdx.x;                    // 128 threads = 128 output cols
    for (int i = tid; i < 5 * HID; i += 128) Ws[i] = W1[i];
    __syncthreads();
    int row0 = blockIdx.x * 16;
    #pragma unroll
    for (int r = 0; r < 16; r++) {
        int row = row0 + r;
        if (row >= N_NODES) return;
        const float* xr = x + (size_t)row * 5;
        float acc = 0.f;
        #pragma unroll
        for (int k = 0; k < 5; k++) acc = fmaf(xr[k], Ws[k * HID + tid], acc);
        g_A[(size_t)row * HID + tid] = acc;
    }
}

// ---------------- self-loop init + bias: B = dinv^2 * A + b ----------------
__global__ __launch_bounds__(256) void k_self_init(const float* __restrict__ bias) {
    int idx = blockIdx.x * blockDim.x + threadIdx.x;       // over N_NODES*32 float4s
    if (idx >= N_NODES * 32) return;
    int node = idx >> 5, c4 = idx & 31;
    float dv = g_dinv[node];
    float s = dv * dv;
    float4 a = ((const float4*)g_A)[idx];
    float4 bb = ((const float4*)bias)[c4];
    float4 o;
    o.x = fmaf(s, a.x, bb.x);
    o.y = fmaf(s, a.y, bb.y);
    o.z = fmaf(s, a.z, bb.z);
    o.w = fmaf(s, a.w, bb.w);
    ((float4*)g_B)[idx] = o;
}

// ---------------- edge scatter: B[dst] += norm * A[src]  (warp per edge) ----------------
__global__ __launch_bounds__(256) void k_scatter(const int* __restrict__ src,
                                                 const int* __restrict__ dst) {
    int g = blockIdx.x * blockDim.x + threadIdx.x;
    int e = g >> 5;
    int lane = threadIdx.x & 31;
    if (e >= N_EDGES) return;
    int s = src[e], d = dst[e];
    float nv = g_norm[e];
    float4 v = ((const float4*)(g_A + (size_t)s * HID))[lane];  // 512B coalesced gather
    float* bp = g_B + (size_t)d * HID + lane * 4;
    atomicAdd(bp + 0, v.x * nv);
    atomicAdd(bp + 1, v.y * nv);
    atomicAdd(bp + 2, v.z * nv);
    atomicAdd(bp + 3, v.w * nv);
}

// ---------------- hidden GEMM: A = relu(B) @ W  (128x128, W + 64-row tile in smem) ----------------
#define GEMM_SMEM ((HID * HID + 64 * HID) * 4)   // 64KB W + 32KB input tile = 98304B

__global__ __launch_bounds__(256) void k_gemm128_relu(const float* __restrict__ W) {
    extern __shared__ float sh[];
    float* Ws = sh;                 // [128][128]
    float* Is = sh + HID * HID;     // [64][128]
    int tid = threadIdx.x;          // 256

    const float4* W4 = (const float4*)W;
    float4* Ws4 = (float4*)Ws;
    #pragma unroll
    for (int i = 0; i < 16; i++) Ws4[tid + 256 * i] = W4[tid + 256 * i];

    int row0 = blockIdx.x * 64;
    float4* Is4 = (float4*)Is;
    #pragma unroll
    for (int i = 0; i < 8; i++) {
        int li = tid + 256 * i;               // 0..2047 float4s
        int r = li >> 5, c = li & 31;
        int grow = row0 + r;
        float4 v = make_float4(0.f, 0.f, 0.f, 0.f);
        if (grow < N_NODES) v = ((const float4*)(g_B + (size_t)grow * HID))[c];
        v.x = fmaxf(v.x, 0.f); v.y = fmaxf(v.y, 0.f);
        v.z = fmaxf(v.z, 0.f); v.w = fmaxf(v.w, 0.f);
        Is4[li] = v;
    }
    __syncthreads();

    int warp = tid >> 5, lane = tid & 31;     // warp -> 8 rows, lane -> 4 cols
    float4 acc[8];
    #pragma unroll
    for (int rr = 0; rr < 8; rr++) acc[rr] = make_float4(0.f, 0.f, 0.f, 0.f);

    const float* isBase = Is + (warp * 8) * HID;
    #pragma unroll 4
    for (int k = 0; k < HID; k++) {
        float4 wv = Ws4[k * 32 + lane];       // conflict-free LDS.128
        #pragma unroll
        for (int rr = 0; rr < 8; rr++) {
            float xv = isBase[rr * HID + k];  // broadcast
            acc[rr].x = fmaf(xv, wv.x, acc[rr].x);
            acc[rr].y = fmaf(xv, wv.y, acc[rr].y);
            acc[rr].z = fmaf(xv, wv.z, acc[rr].z);
            acc[rr].w = fmaf(xv, wv.w, acc[rr].w);
        }
    }
    #pragma unroll
    for (int rr = 0; rr < 8; rr++) {
        int grow = row0 + warp * 8 + rr;
        if (grow < N_NODES)
            ((float4*)(g_A + (size_t)grow * HID))[lane] = acc[rr];
    }
}

// ---------------- final FC: out = relu(B) @ Wfc + bfc  (warp per node) ----------------
__global__ __launch_bounds__(256) void k_final(const float* __restrict__ Wfc,
                                               const float* __restrict__ bfc,
                                               float* __restrict__ out) {
    int g = blockIdx.x * blockDim.x + threadIdx.x;
    int node = g >> 5;
    int lane = g & 31;
    if (node >= N_NODES) return;
    float4 h = ((const float4*)(g_B + (size_t)node * HID))[lane];
    float4 w = ((const float4*)Wfc)[lane];
    float acc = fmaxf(h.x, 0.f) * w.x + fmaxf(h.y, 0.f) * w.y
              + fmaxf(h.z, 0.f) * w.z + fmaxf(h.w, 0.f) * w.w;
    #pragma unroll
    for (int o = 16; o > 0; o >>= 1) acc += __shfl_xor_sync(0xffffffffu, acc, o);
    if (lane == 0) out[node] = acc + bfc[0];
}

// ---------------- launcher ----------------
extern "C" void kernel_launch(void* const* d_in, const int* in_sizes, int n_in,
                              void* d_out, int out_size) {
    const float* x   = (const float*)d_in[0];
    const int*   ei  = (const int*)  d_in[1];
    const float* W1  = (const float*)d_in[2];
    const float* b1  = (const float*)d_in[3];
    const float* W2  = (const float*)d_in[4];
    const float* b2  = (const float*)d_in[5];
    const float* W3  = (const float*)d_in[6];
    const float* b3  = (const float*)d_in[7];
    const float* Wfc = (const float*)d_in[8];
    const float* bfc = (const float*)d_in[9];
    float* out = (float*)d_out;

    const int* src = ei;             // edge_index[0]
    const int* dst = ei + N_EDGES;   // edge_index[1]

    cudaFuncSetAttribute(k_gemm128_relu,
                         cudaFuncAttributeMaxDynamicSharedMemorySize, GEMM_SMEM);

    const int T = 256;
    int nb_nodes  = (N_NODES + T - 1) / T;
    int nb_edges  = (N_EDGES + T - 1) / T;
    int nb_feat   = (N_NODES * 32 + T - 1) / T;   // N*32 float4 lanes
    int nb_scat   = (N_EDGES * 32 + T - 1) / T;   // warp per edge
    int nb_gemm   = (N_NODES + 63) / 64;

    // normalization
    k_deg_init <<<nb_nodes, T>>>();
    k_deg_accum<<<nb_edges, T>>>(dst);
    k_dinv     <<<nb_nodes, T>>>();
    k_norm     <<<nb_edges, T>>>(src, dst);

    // layer 1 (K=5 GEMM)
    k_gemm_in  <<<(N_NODES + 15) / 16, 128>>>(x, W1);
    k_self_init<<<nb_feat, T>>>(b1);
    k_scatter  <<<nb_scat, T>>>(src, dst);

    // layer 2
    k_gemm128_relu<<<nb_gemm, T, GEMM_SMEM>>>(W2);
    k_self_init   <<<nb_feat, T>>>(b2);
    k_scatter     <<<nb_scat, T>>>(src, dst);

    // layer 3
    k_gemm128_relu<<<nb_gemm, T, GEMM_SMEM>>>(W3);
    k_self_init   <<<nb_feat, T>>>(b3);
    k_scatter     <<<nb_scat, T>>>(src, dst);

    // final FC
    k_final<<<nb_feat, T>>>(Wfc, bfc, out);
}

// round 3
// speedup vs baseline: 2.8429x; 2.8429x over previous
#include <cuda_runtime.h>

#define N_NODES 100000
#define N_EDGES 1600000
#define HID 128

// Scratch (no cudaMalloc allowed).
__device__ __align__(16) float g_A[(size_t)N_NODES * HID];   // GEMM output / message source
__device__ __align__(16) float g_B[(size_t)N_NODES * HID];   // aggregation result (pre-activation)
__device__ __align__(16) float g_dinv[N_NODES];
__device__ int   g_cnt[N_NODES];      // in-degree (no self loop)
__device__ int   g_off[N_NODES];      // CSR offsets
__device__ int   g_cur[N_NODES];      // fill cursors
__device__ int   g_srcs[N_EDGES];     // CSR: src node per slot
__device__ float g_wsrc[N_EDGES];     // CSR: dinv[src] per slot

// ---------------- CSR build ----------------
__global__ void k_zero() {
    int i = blockIdx.x * blockDim.x + threadIdx.x;
    if (i < N_NODES) { g_cnt[i] = 0; g_cur[i] = 0; }
}

__global__ void k_deg_count(const int* __restrict__ dst) {
    int e = blockIdx.x * blockDim.x + threadIdx.x;
    if (e < N_EDGES) atomicAdd(&g_cnt[dst[e]], 1);
}

__global__ void k_dinv() {
    int i = blockIdx.x * blockDim.x + threadIdx.x;
    if (i < N_NODES) g_dinv[i] = rsqrtf((float)(g_cnt[i] + 1));  // +1 self loop
}

// Single-block exclusive scan of g_cnt -> g_off (100k elements).
__global__ __launch_bounds__(1024) void k_scan() {
    __shared__ int sh[1024];
    int t = threadIdx.x;
    const int per = (N_NODES + 1023) >> 10;            // 98
    int beg = t * per;
    int end = min(beg + per, N_NODES);
    int s = 0;
    for (int i = beg; i < end; i++) s += g_cnt[i];
    sh[t] = s;
    __syncthreads();
    for (int off = 1; off < 1024; off <<= 1) {
        int v = sh[t];
        int a = (t >= off) ? sh[t - off] : 0;
        __syncthreads();
        sh[t] = v + a;
        __syncthreads();
    }
    int run = (t == 0) ? 0 : sh[t - 1];
    for (int i = beg; i < end; i++) { g_off[i] = run; run += g_cnt[i]; }
}

__global__ void k_fill(const int* __restrict__ src, const int* __restrict__ dst) {
    int e = blockIdx.x * blockDim.x + threadIdx.x;
    if (e >= N_EDGES) return;
    int d = dst[e], s = src[e];
    int pos = g_off[d] + atomicAdd(&g_cur[d], 1);
    g_srcs[pos] = s;
    g_wsrc[pos] = g_dinv[s];
}

// ---------------- layer-1 GEMM: A = x @ W1   (K = 5) ----------------
__global__ __launch_bounds__(128) void k_gemm_in(const float* __restrict__ x,
                                                 const float* __restrict__ W1) {
    __shared__ float Ws[5 * HID];
    int tid = threadIdx.x;
    for (int i = tid; i < 5 * HID; i += 128) Ws[i] = W1[i];
    __syncthreads();
    int row0 = blockIdx.x * 16;
    #pragma unroll
    for (int r = 0; r < 16; r++) {
        int row = row0 + r;
        if (row >= N_NODES) return;
        const float* xr = x + (size_t)row * 5;
        float acc = 0.f;
        #pragma unroll
        for (int k = 0; k < 5; k++) acc = fmaf(xr[k], Ws[k * HID + tid], acc);
        g_A[(size_t)row * HID + tid] = acc;
    }
}

// ---------------- aggregation (atomic-free, CSR gather) ----------------
// B[i] = dinv[i] * ( sum_e dinv[src_e]*A[src_e]  +  dinv[i]*A[i] ) + bias
__global__ __launch_bounds__(256) void k_agg(const float* __restrict__ bias) {
    int g = blockIdx.x * blockDim.x + threadIdx.x;
    int node = g >> 5;
    int lane = g & 31;
    if (node >= N_NODES) return;

    const float4* __restrict__ A4 = (const float4*)g_A;
    float dv = g_dinv[node];
    float4 a = A4[(size_t)node * 32 + lane];
    float4 acc;
    acc.x = dv * a.x; acc.y = dv * a.y; acc.z = dv * a.z; acc.w = dv * a.w;

    int start = g_off[node];
    int cnt   = g_cnt[node];
    for (int j0 = 0; j0 < cnt; j0 += 32) {
        int  rem = cnt - j0;
        bool ok  = lane < rem;
        int   sv = ok ? g_srcs[start + j0 + lane] : 0;
        float wv = ok ? g_wsrc[start + j0 + lane] : 0.f;
        int m = min(32, rem);
        #pragma unroll 4
        for (int j = 0; j < m; j++) {
            int   sj = __shfl_sync(0xffffffffu, sv, j);
            float wj = __shfl_sync(0xffffffffu, wv, j);
            float4 v = A4[(size_t)sj * 32 + lane];
            acc.x = fmaf(wj, v.x, acc.x);
            acc.y = fmaf(wj, v.y, acc.y);
            acc.z = fmaf(wj, v.z, acc.z);
            acc.w = fmaf(wj, v.w, acc.w);
        }
    }
    float4 bb = ((const float4*)bias)[lane];
    float4 o;
    o.x = fmaf(dv, acc.x, bb.x);
    o.y = fmaf(dv, acc.y, bb.y);
    o.z = fmaf(dv, acc.z, bb.z);
    o.w = fmaf(dv, acc.w, bb.w);
    ((float4*)g_B)[(size_t)node * 32 + lane] = o;
}

// ---------------- hidden GEMM: A = relu(B) @ W ----------------
#define GEMM_SMEM ((HID * HID + 64 * HID) * 4)   // 64KB W + 32KB input tile

__global__ __launch_bounds__(256) void k_gemm128_relu(const float* __restrict__ W) {
    extern __shared__ float sh[];
    float* Ws = sh;                 // [128][128]
    float* Is = sh + HID * HID;     // [64][128]
    int tid = threadIdx.x;

    const float4* W4 = (const float4*)W;
    float4* Ws4 = (float4*)Ws;
    #pragma unroll
    for (int i = 0; i < 16; i++) Ws4[tid + 256 * i] = W4[tid + 256 * i];

    int row0 = blockIdx.x * 64;
    float4* Is4 = (float4*)Is;
    #pragma unroll
    for (int i = 0; i < 8; i++) {
        int li = tid + 256 * i;
        int r = li >> 5, c = li & 31;
        int grow = row0 + r;
        float4 v = make_float4(0.f, 0.f, 0.f, 0.f);
        if (grow < N_NODES) v = ((const float4*)(g_B + (size_t)grow * HID))[c];
        v.x = fmaxf(v.x, 0.f); v.y = fmaxf(v.y, 0.f);
        v.z = fmaxf(v.z, 0.f); v.w = fmaxf(v.w, 0.f);
        Is4[li] = v;
    }
    __syncthreads();

    int warp = tid >> 5, lane = tid & 31;
    float4 acc[8];
    #pragma unroll
    for (int rr = 0; rr < 8; rr++) acc[rr] = make_float4(0.f, 0.f, 0.f, 0.f);

    const float* isBase = Is + (warp * 8) * HID;
    #pragma unroll 4
    for (int k = 0; k < HID; k++) {
        float4 wv = Ws4[k * 32 + lane];
        #pragma unroll
        for (int rr = 0; rr < 8; rr++) {
            float xv = isBase[rr * HID + k];
            acc[rr].x = fmaf(xv, wv.x, acc[rr].x);
            acc[rr].y = fmaf(xv, wv.y, acc[rr].y);
            acc[rr].z = fmaf(xv, wv.z, acc[rr].z);
            acc[rr].w = fmaf(xv, wv.w, acc[rr].w);
        }
    }
    #pragma unroll
    for (int rr = 0; rr < 8; rr++) {
        int grow = row0 + warp * 8 + rr;
        if (grow < N_NODES)
            ((float4*)(g_A + (size_t)grow * HID))[lane] = acc[rr];
    }
}

// ---------------- final FC: out = relu(B) @ Wfc + bfc ----------------
__global__ __launch_bounds__(256) void k_final(const float* __restrict__ Wfc,
                                               const float* __restrict__ bfc,
                                               float* __restrict__ out) {
    int g = blockIdx.x * blockDim.x + threadIdx.x;
    int node = g >> 5;
    int lane = g & 31;
    if (node >= N_NODES) return;
    float4 h = ((const float4*)(g_B + (size_t)node * HID))[lane];
    float4 w = ((const float4*)Wfc)[lane];
    float acc = fmaxf(h.x, 0.f) * w.x + fmaxf(h.y, 0.f) * w.y
              + fmaxf(h.z, 0.f) * w.z + fmaxf(h.w, 0.f) * w.w;
    #pragma unroll
    for (int o = 16; o > 0; o >>= 1) acc += __shfl_xor_sync(0xffffffffu, acc, o);
    if (lane == 0) out[node] = acc + bfc[0];
}

// ---------------- launcher ----------------
extern "C" void kernel_launch(void* const* d_in, const int* in_sizes, int n_in,
                              void* d_out, int out_size) {
    const float* x   = (const float*)d_in[0];
    const int*   ei  = (const int*)  d_in[1];
    const float* W1  = (const float*)d_in[2];
    const float* b1  = (const float*)d_in[3];
    const float* W2  = (const float*)d_in[4];
    const float* b2  = (const float*)d_in[5];
    const float* W3  = (const float*)d_in[6];
    const float* b3  = (const float*)d_in[7];
    const float* Wfc = (const float*)d_in[8];
    const float* bfc = (const float*)d_in[9];
    float* out = (float*)d_out;

    const int* src = ei;             // edge_index[0]
    const int* dst = ei + N_EDGES;   // edge_index[1]

    cudaFuncSetAttribute(k_gemm128_relu,
                         cudaFuncAttributeMaxDynamicSharedMemorySize, GEMM_SMEM);

    const int T = 256;
    int nb_nodes = (N_NODES + T - 1) / T;
    int nb_edges = (N_EDGES + T - 1) / T;
    int nb_warps = (N_NODES * 32 + T - 1) / T;    // warp per node
    int nb_gemm  = (N_NODES + 63) / 64;

    // CSR build (once per call, shared by all 3 layers)
    k_zero     <<<nb_nodes, T>>>();
    k_deg_count<<<nb_edges, T>>>(dst);
    k_dinv     <<<nb_nodes, T>>>();
    k_scan     <<<1, 1024>>>();
    k_fill     <<<nb_edges, T>>>(src, dst);

    // layer 1
    k_gemm_in<<<(N_NODES + 15) / 16, 128>>>(x, W1);
    k_agg    <<<nb_warps, T>>>(b1);

    // layer 2
    k_gemm128_relu<<<nb_gemm, T, GEMM_SMEM>>>(W2);
    k_agg         <<<nb_warps, T>>>(b2);

    // layer 3
    k_gemm128_relu<<<nb_gemm, T, GEMM_SMEM>>>(W3);
    k_agg         <<<nb_warps, T>>>(b3);

    // final FC
    k_final<<<nb_warps, T>>>(Wfc, bfc, out);
}

// round 4
// speedup vs baseline: 3.3971x; 1.1950x over previous
#include <cuda_runtime.h>

#define N_NODES 100000
#define N_EDGES 1600000
#define HID 128
#define SCAN_B 1024
#define NB_SCAN ((N_NODES + SCAN_B - 1) / SCAN_B)   // 98

// Scratch (no cudaMalloc allowed).
__device__ __align__(16) float g_A[(size_t)N_NODES * HID];   // GEMM output / message source
__device__ __align__(16) float g_B[(size_t)N_NODES * HID];   // aggregation result (pre-activation)
__device__ __align__(16) float g_dinv[N_NODES];
__device__ int   g_cnt[N_NODES];      // in-degree (no self loop)
__device__ int   g_off[N_NODES];      // CSR offsets
__device__ int   g_cur[N_NODES];      // fill cursors
__device__ int   g_bsum[NB_SCAN];     // per-block sums
__device__ int   g_boff[NB_SCAN];     // per-block exclusive offsets
__device__ int   g_srcs[N_EDGES];     // CSR: src node per slot
__device__ float g_wsrc[N_EDGES];     // CSR: dinv[src] per slot

// ---------------- CSR build ----------------
__global__ void k_zero() {
    int i = blockIdx.x * blockDim.x + threadIdx.x;
    if (i < N_NODES) { g_cnt[i] = 0; g_cur[i] = 0; }
}

__global__ void k_deg_count(const int* __restrict__ dst) {
    int e = blockIdx.x * blockDim.x + threadIdx.x;
    if (e < N_EDGES) atomicAdd(&g_cnt[dst[e]], 1);
}

__global__ void k_dinv() {
    int i = blockIdx.x * blockDim.x + threadIdx.x;
    if (i < N_NODES) g_dinv[i] = rsqrtf((float)(g_cnt[i] + 1));  // +1 self loop
}

// Stage 1: per-block sums of g_cnt (98 blocks x 1024)
__global__ __launch_bounds__(SCAN_B) void k_bsum() {
    __shared__ int sh[SCAN_B];
    int t = threadIdx.x;
    int i = blockIdx.x * SCAN_B + t;
    sh[t] = (i < N_NODES) ? g_cnt[i] : 0;
    __syncthreads();
    #pragma unroll
    for (int off = SCAN_B / 2; off > 0; off >>= 1) {
        if (t < off) sh[t] += sh[t + off];
        __syncthreads();
    }
    if (t == 0) g_bsum[blockIdx.x] = sh[0];
}

// Stage 2: exclusive scan of 98 block sums (1 block, 128 threads)
__global__ __launch_bounds__(128) void k_bscan() {
    __shared__ int sh[128];
    int t = threadIdx.x;
    sh[t] = (t < NB_SCAN) ? g_bsum[t] : 0;
    __syncthreads();
    #pragma unroll
    for (int off = 1; off < 128; off <<= 1) {
        int v = sh[t];
        int a = (t >= off) ? sh[t - off] : 0;
        __syncthreads();
        sh[t] = v + a;
        __syncthreads();
    }
    if (t < NB_SCAN) g_boff[t] = (t == 0) ? 0 : sh[t - 1];
}

// Stage 3: in-block exclusive scan + block offset -> g_off
__global__ __launch_bounds__(SCAN_B) void k_boff() {
    __shared__ int sh[SCAN_B];
    int t = threadIdx.x;
    int i = blockIdx.x * SCAN_B + t;
    int v = (i < N_NODES) ? g_cnt[i] : 0;
    sh[t] = v;
    __syncthreads();
    #pragma unroll
    for (int off = 1; off < SCAN_B; off <<= 1) {
        int cur = sh[t];
        int a = (t >= off) ? sh[t - off] : 0;
        __syncthreads();
        sh[t] = cur + a;
        __syncthreads();
    }
    if (i < N_NODES) g_off[i] = g_boff[blockIdx.x] + sh[t] - v;   // exclusive
}

__global__ void k_fill(const int* __restrict__ src, const int* __restrict__ dst) {
    int e = blockIdx.x * blockDim.x + threadIdx.x;
    if (e >= N_EDGES) return;
    int d = dst[e], s = src[e];
    int pos = g_off[d] + atomicAdd(&g_cur[d], 1);
    g_srcs[pos] = s;
    g_wsrc[pos] = g_dinv[s];
}

// ---------------- layer-1 GEMM: A = x @ W1   (K = 5) ----------------
__global__ __launch_bounds__(128) void k_gemm_in(const float* __restrict__ x,
                                                 const float* __restrict__ W1) {
    __shared__ float Ws[5 * HID];
    int tid = threadIdx.x;
    for (int i = tid; i < 5 * HID; i += 128) Ws[i] = W1[i];
    __syncthreads();
    int row0 = blockIdx.x * 16;
    #pragma unroll
    for (int r = 0; r < 16; r++) {
        int row = row0 + r;
        if (row >= N_NODES) return;
        const float* xr = x + (size_t)row * 5;
        float acc = 0.f;
        #pragma unroll
        for (int k = 0; k < 5; k++) acc = fmaf(xr[k], Ws[k * HID + tid], acc);
        g_A[(size_t)row * HID + tid] = acc;
    }
}

// ---------------- aggregation (atomic-free, CSR gather) ----------------
// B[i] = dinv[i] * ( sum_e dinv[src_e]*A[src_e]  +  dinv[i]*A[i] ) + bias
__global__ __launch_bounds__(256) void k_agg(const float* __restrict__ bias) {
    int g = blockIdx.x * blockDim.x + threadIdx.x;
    int node = g >> 5;
    int lane = g & 31;
    if (node >= N_NODES) return;

    const float4* __restrict__ A4 = (const float4*)g_A;
    float dv = g_dinv[node];
    float4 a = A4[(size_t)node * 32 + lane];
    float4 acc;
    acc.x = dv * a.x; acc.y = dv * a.y; acc.z = dv * a.z; acc.w = dv * a.w;

    int start = g_off[node];
    int cnt   = g_cnt[node];
    for (int j0 = 0; j0 < cnt; j0 += 32) {
        int  rem = cnt - j0;
        bool ok  = lane < rem;
        int   sv = ok ? g_srcs[start + j0 + lane] : 0;
        float wv = ok ? g_wsrc[start + j0 + lane] : 0.f;
        int m = min(32, rem);
        #pragma unroll 4
        for (int j = 0; j < m; j++) {
            int   sj = __shfl_sync(0xffffffffu, sv, j);
            float wj = __shfl_sync(0xffffffffu, wv, j);
            float4 v = A4[(size_t)sj * 32 + lane];
            acc.x = fmaf(wj, v.x, acc.x);
            acc.y = fmaf(wj, v.y, acc.y);
            acc.z = fmaf(wj, v.z, acc.z);
            acc.w = fmaf(wj, v.w, acc.w);
        }
    }
    float4 bb = ((const float4*)bias)[lane];
    float4 o;
    o.x = fmaf(dv, acc.x, bb.x);
    o.y = fmaf(dv, acc.y, bb.y);
    o.z = fmaf(dv, acc.z, bb.z);
    o.w = fmaf(dv, acc.w, bb.w);
    ((float4*)g_B)[(size_t)node * 32 + lane] = o;
}

// ---------------- hidden GEMM: A = relu(B) @ W ----------------
#define GEMM_SMEM ((HID * HID + 64 * HID) * 4)   // 64KB W + 32KB input tile

__global__ __launch_bounds__(256) void k_gemm128_relu(const float* __restrict__ W) {
    extern __shared__ float sh[];
    float* Ws = sh;                 // [128][128]
    float* Is = sh + HID * HID;     // [64][128]
    int tid = threadIdx.x;

    const float4* W4 = (const float4*)W;
    float4* Ws4 = (float4*)Ws;
    #pragma unroll
    for (int i = 0; i < 16; i++) Ws4[tid + 256 * i] = W4[tid + 256 * i];

    int row0 = blockIdx.x * 64;
    float4* Is4 = (float4*)Is;
    #pragma unroll
    for (int i = 0; i < 8; i++) {
        int li = tid + 256 * i;
        int r = li >> 5, c = li & 31;
        int grow = row0 + r;
        float4 v = make_float4(0.f, 0.f, 0.f, 0.f);
        if (grow < N_NODES) v = ((const float4*)(g_B + (size_t)grow * HID))[c];
        v.x = fmaxf(v.x, 0.f); v.y = fmaxf(v.y, 0.f);
        v.z = fmaxf(v.z, 0.f); v.w = fmaxf(v.w, 0.f);
        Is4[li] = v;
    }
    __syncthreads();

    int warp = tid >> 5, lane = tid & 31;
    float4 acc[8];
    #pragma unroll
    for (int rr = 0; rr < 8; rr++) acc[rr] = make_float4(0.f, 0.f, 0.f, 0.f);

    const float* isBase = Is + (warp * 8) * HID;
    #pragma unroll 4
    for (int k = 0; k < HID; k++) {
        float4 wv = Ws4[k * 32 + lane];
        #pragma unroll
        for (int rr = 0; rr < 8; rr++) {
            float xv = isBase[rr * HID + k];
            acc[rr].x = fmaf(xv, wv.x, acc[rr].x);
            acc[rr].y = fmaf(xv, wv.y, acc[rr].y);
            acc[rr].z = fmaf(xv, wv.z, acc[rr].z);
            acc[rr].w = fmaf(xv, wv.w, acc[rr].w);
        }
    }
    #pragma unroll
    for (int rr = 0; rr < 8; rr++) {
        int grow = row0 + warp * 8 + rr;
        if (grow < N_NODES)
            ((float4*)(g_A + (size_t)grow * HID))[lane] = acc[rr];
    }
}

// ---------------- final FC: out = relu(B) @ Wfc + bfc ----------------
__global__ __launch_bounds__(256) void k_final(const float* __restrict__ Wfc,
                                               const float* __restrict__ bfc,
                                               float* __restrict__ out) {
    int g = blockIdx.x * blockDim.x + threadIdx.x;
    int node = g >> 5;
    int lane = g & 31;
    if (node >= N_NODES) return;
    float4 h = ((const float4*)(g_B + (size_t)node * HID))[lane];
    float4 w = ((const float4*)Wfc)[lane];
    float acc = fmaxf(h.x, 0.f) * w.x + fmaxf(h.y, 0.f) * w.y
              + fmaxf(h.z, 0.f) * w.z + fmaxf(h.w, 0.f) * w.w;
    #pragma unroll
    for (int o = 16; o > 0; o >>= 1) acc += __shfl_xor_sync(0xffffffffu, acc, o);
    if (lane == 0) out[node] = acc + bfc[0];
}

// ---------------- launcher ----------------
extern "C" void kernel_launch(void* const* d_in, const int* in_sizes, int n_in,
                              void* d_out, int out_size) {
    const float* x   = (const float*)d_in[0];
    const int*   ei  = (const int*)  d_in[1];
    const float* W1  = (const float*)d_in[2];
    const float* b1  = (const float*)d_in[3];
    const float* W2  = (const float*)d_in[4];
    const float* b2  = (const float*)d_in[5];
    const float* W3  = (const float*)d_in[6];
    const float* b3  = (const float*)d_in[7];
    const float* Wfc = (const float*)d_in[8];
    const float* bfc = (const float*)d_in[9];
    float* out = (float*)d_out;

    const int* src = ei;             // edge_index[0]
    const int* dst = ei + N_EDGES;   // edge_index[1]

    cudaFuncSetAttribute(k_gemm128_relu,
                         cudaFuncAttributeMaxDynamicSharedMemorySize, GEMM_SMEM);

    const int T = 256;
    int nb_nodes = (N_NODES + T - 1) / T;
    int nb_edges = (N_EDGES + T - 1) / T;
    int nb_warps = (N_NODES * 32 + T - 1) / T;    // warp per node
    int nb_gemm  = (N_NODES + 63) / 64;

    // CSR build (once per call, shared by all 3 layers)
    k_zero     <<<nb_nodes, T>>>();
    k_deg_count<<<nb_edges, T>>>(dst);
    k_dinv     <<<nb_nodes, T>>>();
    k_bsum     <<<NB_SCAN, SCAN_B>>>();
    k_bscan    <<<1, 128>>>();
    k_boff     <<<NB_SCAN, SCAN_B>>>();
    k_fill     <<<nb_edges, T>>>(src, dst);

    // layer 1
    k_gemm_in<<<(N_NODES + 15) / 16, 128>>>(x, W1);
    k_agg    <<<nb_warps, T>>>(b1);

    // layer 2
    k_gemm128_relu<<<nb_gemm, T, GEMM_SMEM>>>(W2);
    k_agg         <<<nb_warps, T>>>(b2);

    // layer 3
    k_gemm128_relu<<<nb_gemm, T, GEMM_SMEM>>>(W3);
    k_agg         <<<nb_warps, T>>>(b3);

    // final FC
    k_final<<<nb_warps, T>>>(Wfc, bfc, out);
}

// round 5
// speedup vs baseline: 3.9685x; 1.1682x over previous
#include <cuda_runtime.h>

#define N_NODES 100000
#define N_EDGES 1600000
#define HID 128
#define SCAN_B 1024
#define NB_SCAN ((N_NODES + SCAN_B - 1) / SCAN_B)   // 98

typedef unsigned long long u64;

// Scratch (no cudaMalloc allowed).
__device__ __align__(16) float g_A[(size_t)N_NODES * HID];   // GEMM output / message source
__device__ __align__(16) float g_B[(size_t)N_NODES * HID];   // aggregation result (pre-activation)
__device__ __align__(16) float g_XA[(size_t)N_NODES * 5];    // aggregated raw input (layer-1 reorder)
__device__ __align__(16) float g_dinv[N_NODES];
__device__ int   g_cnt[N_NODES];
__device__ int   g_off[N_NODES];
__device__ int   g_cur[N_NODES];
__device__ int   g_bsum[NB_SCAN];
__device__ int   g_boff[NB_SCAN];
__device__ int   g_srcs[N_EDGES];
__device__ float g_wsrc[N_EDGES];

#define FFMA2(acc, a, b) asm("fma.rn.f32x2 %0, %1, %2, %0;" : "+l"(acc) : "l"(a), "l"(b))

union F2U { u64 u; float2 f; };

// ---------------- CSR build ----------------
__global__ void k_zero() {
    int i = blockIdx.x * blockDim.x + threadIdx.x;
    if (i < N_NODES) { g_cnt[i] = 0; g_cur[i] = 0; }
}

__global__ void k_deg_count(const int* __restrict__ dst) {
    int e = blockIdx.x * blockDim.x + threadIdx.x;
    if (e < N_EDGES) atomicAdd(&g_cnt[dst[e]], 1);
}

__global__ void k_dinv() {
    int i = blockIdx.x * blockDim.x + threadIdx.x;
    if (i < N_NODES) g_dinv[i] = rsqrtf((float)(g_cnt[i] + 1));
}

__global__ __launch_bounds__(SCAN_B) void k_bsum() {
    __shared__ int sh[SCAN_B];
    int t = threadIdx.x;
    int i = blockIdx.x * SCAN_B + t;
    sh[t] = (i < N_NODES) ? g_cnt[i] : 0;
    __syncthreads();
    #pragma unroll
    for (int off = SCAN_B / 2; off > 0; off >>= 1) {
        if (t < off) sh[t] += sh[t + off];
        __syncthreads();
    }
    if (t == 0) g_bsum[blockIdx.x] = sh[0];
}

__global__ __launch_bounds__(128) void k_bscan() {
    __shared__ int sh[128];
    int t = threadIdx.x;
    sh[t] = (t < NB_SCAN) ? g_bsum[t] : 0;
    __syncthreads();
    #pragma unroll
    for (int off = 1; off < 128; off <<= 1) {
        int v = sh[t];
        int a = (t >= off) ? sh[t - off] : 0;
        __syncthreads();
        sh[t] = v + a;
        __syncthreads();
    }
    if (t < NB_SCAN) g_boff[t] = (t == 0) ? 0 : sh[t - 1];
}

__global__ __launch_bounds__(SCAN_B) void k_boff() {
    __shared__ int sh[SCAN_B];
    int t = threadIdx.x;
    int i = blockIdx.x * SCAN_B + t;
    int v = (i < N_NODES) ? g_cnt[i] : 0;
    sh[t] = v;
    __syncthreads();
    #pragma unroll
    for (int off = 1; off < SCAN_B; off <<= 1) {
        int cur = sh[t];
        int a = (t >= off) ? sh[t - off] : 0;
        __syncthreads();
        sh[t] = cur + a;
        __syncthreads();
    }
    if (i < N_NODES) g_off[i] = g_boff[blockIdx.x] + sh[t] - v;
}

__global__ void k_fill(const int* __restrict__ src, const int* __restrict__ dst) {
    int e = blockIdx.x * blockDim.x + threadIdx.x;
    if (e >= N_EDGES) return;
    int d = dst[e], s = src[e];
    int pos = g_off[d] + atomicAdd(&g_cur[d], 1);
    g_srcs[pos] = s;
    g_wsrc[pos] = g_dinv[s];
}

// ---------------- layer-1: aggregate raw 5-wide input: XA = Â X ----------------
__global__ __launch_bounds__(256) void k_agg_x(const float* __restrict__ x) {
    int i = blockIdx.x * blockDim.x + threadIdx.x;
    if (i >= N_NODES) return;
    float dv = g_dinv[i];
    float acc[5];
    #pragma unroll
    for (int k = 0; k < 5; k++) acc[k] = dv * x[(size_t)i * 5 + k];
    int start = g_off[i], cnt = g_cnt[i];
    for (int j = 0; j < cnt; j++) {
        int s = g_srcs[start + j];
        float w = g_wsrc[start + j];
        #pragma unroll
        for (int k = 0; k < 5; k++) acc[k] = fmaf(w, x[(size_t)s * 5 + k], acc[k]);
    }
    #pragma unroll
    for (int k = 0; k < 5; k++) g_XA[(size_t)i * 5 + k] = dv * acc[k];
}

// ---------------- layer-1 GEMM: B = XA @ W1 + b1  (pre-activation) ----------------
__global__ __launch_bounds__(128) void k_gemm_in(const float* __restrict__ W1,
                                                 const float* __restrict__ b1) {
    __shared__ float Ws[5 * HID];
    int tid = threadIdx.x;
    for (int i = tid; i < 5 * HID; i += 128) Ws[i] = W1[i];
    __syncthreads();
    float bb = b1[tid];
    int row0 = blockIdx.x * 16;
    #pragma unroll
    for (int r = 0; r < 16; r++) {
        int row = row0 + r;
        if (row >= N_NODES) return;
        const float* xr = g_XA + (size_t)row * 5;
        float acc = bb;
        #pragma unroll
        for (int k = 0; k < 5; k++) acc = fmaf(xr[k], Ws[k * HID + tid], acc);
        g_B[(size_t)row * HID + tid] = acc;
    }
}

// ---------------- aggregation (atomic-free, CSR gather) ----------------
__global__ __launch_bounds__(256) void k_agg(const float* __restrict__ bias) {
    int g = blockIdx.x * blockDim.x + threadIdx.x;
    int node = g >> 5;
    int lane = g & 31;
    if (node >= N_NODES) return;

    const float4* __restrict__ A4 = (const float4*)g_A;
    float dv = g_dinv[node];
    float4 a = A4[(size_t)node * 32 + lane];
    float4 acc;
    acc.x = dv * a.x; acc.y = dv * a.y; acc.z = dv * a.z; acc.w = dv * a.w;

    int start = g_off[node];
    int cnt   = g_cnt[node];
    for (int j0 = 0; j0 < cnt; j0 += 32) {
        int  rem = cnt - j0;
        bool ok  = lane < rem;
        int   sv = ok ? g_srcs[start + j0 + lane] : 0;
        float wv = ok ? g_wsrc[start + j0 + lane] : 0.f;
        int m = min(32, rem);
        #pragma unroll 4
        for (int j = 0; j < m; j++) {
            int   sj = __shfl_sync(0xffffffffu, sv, j);
            float wj = __shfl_sync(0xffffffffu, wv, j);
            float4 v = A4[(size_t)sj * 32 + lane];
            acc.x = fmaf(wj, v.x, acc.x);
            acc.y = fmaf(wj, v.y, acc.y);
            acc.z = fmaf(wj, v.z, acc.z);
            acc.w = fmaf(wj, v.w, acc.w);
        }
    }
    float4 bb = ((const float4*)bias)[lane];
    float4 o;
    o.x = fmaf(dv, acc.x, bb.x);
    o.y = fmaf(dv, acc.y, bb.y);
    o.z = fmaf(dv, acc.z, bb.z);
    o.w = fmaf(dv, acc.w, bb.w);
    ((float4*)g_B)[(size_t)node * 32 + lane] = o;
}

// ---------------- layer-3 aggregation fused with final FC ----------------
// out[node] = relu(dinv*(gather)+b3) . Wfc + bfc
__global__ __launch_bounds__(256) void k_agg_final(const float* __restrict__ bias,
                                                   const float* __restrict__ Wfc,
                                                   const float* __restrict__ bfc,
                                                   float* __restrict__ out) {
    int g = blockIdx.x * blockDim.x + threadIdx.x;
    int node = g >> 5;
    int lane = g & 31;
    if (node >= N_NODES) return;

    const float4* __restrict__ A4 = (const float4*)g_A;
    float dv = g_dinv[node];
    float4 a = A4[(size_t)node * 32 + lane];
    float4 acc;
    acc.x = dv * a.x; acc.y = dv * a.y; acc.z = dv * a.z; acc.w = dv * a.w;

    int start = g_off[node];
    int cnt   = g_cnt[node];
    for (int j0 = 0; j0 < cnt; j0 += 32) {
        int  rem = cnt - j0;
        bool ok  = lane < rem;
        int   sv = ok ? g_srcs[start + j0 + lane] : 0;
        float wv = ok ? g_wsrc[start + j0 + lane] : 0.f;
        int m = min(32, rem);
        #pragma unroll 4
        for (int j = 0; j < m; j++) {
            int   sj = __shfl_sync(0xffffffffu, sv, j);
            float wj = __shfl_sync(0xffffffffu, wv, j);
            float4 v = A4[(size_t)sj * 32 + lane];
            acc.x = fmaf(wj, v.x, acc.x);
            acc.y = fmaf(wj, v.y, acc.y);
            acc.z = fmaf(wj, v.z, acc.z);
            acc.w = fmaf(wj, v.w, acc.w);
        }
    }
    float4 bb = ((const float4*)bias)[lane];
    float4 w  = ((const float4*)Wfc)[lane];
    float dot = fmaxf(fmaf(dv, acc.x, bb.x), 0.f) * w.x
              + fmaxf(fmaf(dv, acc.y, bb.y), 0.f) * w.y
              + fmaxf(fmaf(dv, acc.z, bb.z), 0.f) * w.z
              + fmaxf(fmaf(dv, acc.w, bb.w), 0.f) * w.w;
    #pragma unroll
    for (int o = 16; o > 0; o >>= 1) dot += __shfl_xor_sync(0xffffffffu, dot, o);
    if (lane == 0) out[node] = dot + bfc[0];
}

// ---------------- hidden GEMM: A = relu(B) @ W  (f32x2, transposed-W smem) ----------------
#define WT_PITCH 130
#define GEMM_SMEM ((HID * WT_PITCH + 64 * HID) * 4)   // 66560 + 32768 = 99328 B

__global__ __launch_bounds__(256) void k_gemm128_relu(const float* __restrict__ W) {
    extern __shared__ float sh[];
    float* WsT = sh;                      // [128 cols][130 k]  (pitch 130)
    float* Is  = sh + HID * WT_PITCH;     // [64 rows][128 k]
    int tid = threadIdx.x;

    // Transpose W[k][c] -> WsT[c][k]
    const float4* W4 = (const float4*)W;
    #pragma unroll
    for (int i = 0; i < 16; i++) {
        int idx4 = tid + 256 * i;          // 0..4095
        int k = idx4 >> 5;                 // row of W
        int c0 = (idx4 & 31) * 4;          // 4 consecutive cols
        float4 v = W4[idx4];
        WsT[(c0 + 0) * WT_PITCH + k] = v.x;
        WsT[(c0 + 1) * WT_PITCH + k] = v.y;
        WsT[(c0 + 2) * WT_PITCH + k] = v.z;
        WsT[(c0 + 3) * WT_PITCH + k] = v.w;
    }

    int row0 = blockIdx.x * 64;
    float4* Is4 = (float4*)Is;
    #pragma unroll
    for (int i = 0; i < 8; i++) {
        int li = tid + 256 * i;
        int r = li >> 5, c = li & 31;
        int grow = row0 + r;
        float4 v = make_float4(0.f, 0.f, 0.f, 0.f);
        if (grow < N_NODES) v = ((const float4*)(g_B + (size_t)grow * HID))[c];
        v.x = fmaxf(v.x, 0.f); v.y = fmaxf(v.y, 0.f);
        v.z = fmaxf(v.z, 0.f); v.w = fmaxf(v.w, 0.f);
        Is4[li] = v;
    }
    __syncthreads();

    int warp = tid >> 5, lane = tid & 31;
    int r0 = warp * 8;
    // acc[rr][cg]: pair dim = k (lo = even-k partial, hi = odd-k partial)
    u64 acc[8][4];
    #pragma unroll
    for (int rr = 0; rr < 8; rr++)
        #pragma unroll
        for (int cg = 0; cg < 4; cg++) acc[rr][cg] = 0ull;

    const float* isBase = Is + r0 * HID;
    #pragma unroll 4
    for (int kp = 0; kp < HID / 2; kp++) {
        u64 wv[4];
        #pragma unroll
        for (int cg = 0; cg < 4; cg++)
            wv[cg] = *(const u64*)&WsT[(lane + 32 * cg) * WT_PITCH + 2 * kp];
        #pragma unroll
        for (int rr = 0; rr < 8; rr++) {
            u64 xv = *(const u64*)&isBase[rr * HID + 2 * kp];   // warp broadcast
            #pragma unroll
            for (int cg = 0; cg < 4; cg++) FFMA2(acc[rr][cg], xv, wv[cg]);
        }
    }

    #pragma unroll
    for (int rr = 0; rr < 8; rr++) {
        int grow = row0 + r0 + rr;
        if (grow >= N_NODES) break;
        float* ap = g_A + (size_t)grow * HID;
        #pragma unroll
        for (int cg = 0; cg < 4; cg++) {
            F2U u; u.u = acc[rr][cg];
            ap[lane + 32 * cg] = u.f.x + u.f.y;
        }
    }
}

// ---------------- launcher ----------------
extern "C" void kernel_launch(void* const* d_in, const int* in_sizes, int n_in,
                              void* d_out, int out_size) {
    const float* x   = (const float*)d_in[0];
    const int*   ei  = (const int*)  d_in[1];
    const float* W1  = (const float*)d_in[2];
    const float* b1  = (const float*)d_in[3];
    const float* W2  = (const float*)d_in[4];
    const float* b2  = (const float*)d_in[5];
    const float* W3  = (const float*)d_in[6];
    const float* b3  = (const float*)d_in[7];
    const float* Wfc = (const float*)d_in[8];
    const float* bfc = (const float*)d_in[9];
    float* out = (float*)d_out;

    const int* src = ei;             // edge_index[0]
    const int* dst = ei + N_EDGES;   // edge_index[1]

    cudaFuncSetAttribute(k_gemm128_relu,
                         cudaFuncAttributeMaxDynamicSharedMemorySize, GEMM_SMEM);

    const int T = 256;
    int nb_nodes = (N_NODES + T - 1) / T;
    int nb_edges = (N_EDGES + T - 1) / T;
    int nb_warps = (N_NODES * 32 + T - 1) / T;    // warp per node
    int nb_gemm  = (N_NODES + 63) / 64;

    // CSR build
    k_zero     <<<nb_nodes, T>>>();
    k_deg_count<<<nb_edges, T>>>(dst);
    k_dinv     <<<nb_nodes, T>>>();
    k_bsum     <<<NB_SCAN, SCAN_B>>>();
    k_bscan    <<<1, 128>>>();
    k_boff     <<<NB_SCAN, SCAN_B>>>();
    k_fill     <<<nb_edges, T>>>(src, dst);

    // layer 1 (reordered: aggregate 5-wide input first, then GEMM+bias)
    k_agg_x  <<<nb_nodes, T>>>(x);
    k_gemm_in<<<(N_NODES + 15) / 16, 128>>>(W1, b1);

    // layer 2
    k_gemm128_relu<<<nb_gemm, T, GEMM_SMEM>>>(W2);
    k_agg         <<<nb_warps, T>>>(b2);

    // layer 3 + final FC fused
    k_gemm128_relu<<<nb_gemm, T, GEMM_SMEM>>>(W3);
    k_agg_final   <<<nb_warps, T>>>(b3, Wfc, bfc, out);
}